// round 17
// baseline (speedup 1.0000x reference)
#include <cuda_runtime.h>
#include <cuda_fp16.h>
#include <math.h>
#include <stdint.h>

#define N_TOKENS 16384
#define HIDDEN   4096
#define NEXP     64
#define TOPK     8

#define BM       128          // tokens per CTA
#define TK       64           // k per tile
#define NT       (HIDDEN/TK)  // 64 tiles
#define NTH      512          // warps 0-7 consumers (4Mx2N, 32x32), 8-15 producers

// smem (bytes)
#define A_TERM   16384        // fp16 A term: 128 x 64 x 2B
#define A16_SLOT (2*A_TERM)   // 32768
#define B_TERM   8192
#define B_SLOT   16384
#define SMEM_BYTES (1024 + 2*A16_SLOT + 2*B_SLOT)   // 99328
#define CRS      72           // epilogue C row stride (floats)

#define SCALE_IN   2048.0f            // 2^11 on both x and W
#define SCALE_OUT  (1.0f/4194304.0f)  // exact 2^-22

// pre-split, pre-swizzled W (x2048, 2 fp16 terms): [tile][term][e][64k] (1 MB)
__device__ __align__(16) unsigned char g_wb[NT * B_SLOT];

// ---------------- helpers ----------------
__device__ __forceinline__ uint32_t smem_u32(const void* p) {
    uint32_t a;
    asm("{ .reg .u64 t; cvta.to.shared.u64 t, %1; cvt.u32.u64 %0, t; }" : "=r"(a) : "l"(p));
    return a;
}
__device__ __forceinline__ uint32_t sw128(uint32_t o) { return o ^ ((o >> 3) & 0x70); }

#define PACK_F16X2(res, lo, hi) \
    asm("cvt.rn.f16x2.f32 %0, %1, %2;" : "=r"(res) : "f"(hi), "f"(lo))

__device__ __forceinline__ void sts64(uint32_t a, uint32_t x, uint32_t y) {
    asm volatile("st.shared.v2.b32 [%0], {%1,%2};" :: "r"(a), "r"(x), "r"(y) : "memory");
}
__device__ __forceinline__ void cp_async16(uint32_t dst, const void* src) {
    asm volatile("cp.async.cg.shared.global [%0], [%1], 16;" :: "r"(dst), "l"(src) : "memory");
}
#define CP_COMMIT() asm volatile("cp.async.commit_group;" ::: "memory")
#define CP_WAIT0()  asm volatile("cp.async.wait_group 0;" ::: "memory")

__device__ __forceinline__ void ldsm_x4(uint32_t r[4], uint32_t addr) {
    asm volatile("ldmatrix.sync.aligned.m8n8.x4.shared.b16 {%0,%1,%2,%3}, [%4];"
        : "=r"(r[0]), "=r"(r[1]), "=r"(r[2]), "=r"(r[3]) : "r"(addr));
}
__device__ __forceinline__ void mma16816(float c[4], const uint32_t a[4],
                                         uint32_t b0, uint32_t b1) {
    asm volatile("mma.sync.aligned.m16n8k16.row.col.f32.f16.f16.f32 "
        "{%0,%1,%2,%3}, {%4,%5,%6,%7}, {%8,%9}, {%0,%1,%2,%3};"
        : "+f"(c[0]), "+f"(c[1]), "+f"(c[2]), "+f"(c[3])
        : "r"(a[0]), "r"(a[1]), "r"(a[2]), "r"(a[3]), "r"(b0), "r"(b1));
}

// x*2^11 = h0 + h1 (+ eps ~2^-22 rel). h0 roundtrip exact; r exact (Sterbenz).
__device__ __forceinline__ void splitf16(float v, float& f0, float& r) {
    f0 = __half2float(__float2half_rn(v));
    r  = v - f0;
}

// ---------------- W pre-split kernel ----------------
__global__ void wsplit_kernel(const float* __restrict__ W) {
    const int t = blockIdx.x;                 // tile (64 k)
    unsigned char* dst = g_wb + (size_t)t * B_SLOT;
    for (int item = threadIdx.x; item < NEXP * 16; item += blockDim.x) {
        const int e = item >> 4;
        const int k = (item & 15) * 4;
        float4 w = *(const float4*)(W + (size_t)e * HIDDEN + t * TK + k);
        float v[4] = {w.x * SCALE_IN, w.y * SCALE_IN, w.z * SCALE_IN, w.w * SCALE_IN};
        float f0[4], r[4];
#pragma unroll
        for (int i = 0; i < 4; i++) splitf16(v[i], f0[i], r[i]);
        uint32_t u0a, u0b, u1a, u1b;
        PACK_F16X2(u0a, f0[0], f0[1]); PACK_F16X2(u0b, f0[2], f0[3]);
        PACK_F16X2(u1a, r[0],  r[1]);  PACK_F16X2(u1b, r[2],  r[3]);
        const uint32_t off = sw128((uint32_t)(e * 128 + k * 2));
        *(uint2*)(dst + 0 * B_TERM + off) = make_uint2(u0a, u0b);
        *(uint2*)(dst + 1 * B_TERM + off) = make_uint2(u1a, u1b);
    }
}

// MMA over one 64-k tile, warp tile 32x32, merged accumulator (R13-proven).
__device__ __forceinline__ void mma_stage(
    uint32_t Ab, uint32_t Bb, float acc[2][4][4],
    uint32_t arow0, uint32_t arow1, uint32_t brow0, uint32_t brow1,
    uint32_t colb, uint32_t swz)
{
#pragma unroll
    for (int k16 = 0; k16 < 4; k16++) {
        const uint32_t coff = (colb + 32u * k16) ^ swz;

        uint32_t B00[4], B01[4], B10[4], B11[4];
        ldsm_x4(B00, Bb + 0 * B_TERM + brow0 + coff);
        ldsm_x4(B01, Bb + 0 * B_TERM + brow1 + coff);
        ldsm_x4(B10, Bb + 1 * B_TERM + brow0 + coff);
        ldsm_x4(B11, Bb + 1 * B_TERM + brow1 + coff);

        uint32_t A00[4], A01[4], A10[4], A11[4];
        ldsm_x4(A00, Ab + 0 * A_TERM + arow0 + coff);
        ldsm_x4(A01, Ab + 0 * A_TERM + arow1 + coff);
        ldsm_x4(A10, Ab + 1 * A_TERM + arow0 + coff);
        ldsm_x4(A11, Ab + 1 * A_TERM + arow1 + coff);

#pragma unroll
        for (int im = 0; im < 2; im++) {
            const uint32_t* Ah0 = (im == 0) ? A00 : A01;
            const uint32_t* Ah1 = (im == 0) ? A10 : A11;
            mma16816(acc[im][0], Ah0, B00[0], B00[2]);
            mma16816(acc[im][1], Ah0, B00[1], B00[3]);
            mma16816(acc[im][2], Ah0, B01[0], B01[2]);
            mma16816(acc[im][3], Ah0, B01[1], B01[3]);
            mma16816(acc[im][0], Ah0, B10[0], B10[2]);
            mma16816(acc[im][1], Ah0, B10[1], B10[3]);
            mma16816(acc[im][2], Ah0, B11[0], B11[2]);
            mma16816(acc[im][3], Ah0, B11[1], B11[3]);
            mma16816(acc[im][0], Ah1, B00[0], B00[2]);
            mma16816(acc[im][1], Ah1, B00[1], B00[3]);
            mma16816(acc[im][2], Ah1, B01[0], B01[2]);
            mma16816(acc[im][3], Ah1, B01[1], B01[3]);
        }
    }
}

#define DRAIN()                                                \
    do {                                                       \
        _Pragma("unroll")                                      \
        for (int _i = 0; _i < 2; _i++)                         \
        _Pragma("unroll")                                      \
        for (int _j = 0; _j < 4; _j++)                         \
        _Pragma("unroll")                                      \
        for (int _q = 0; _q < 4; _q++) {                       \
            sum[_i][_j][_q] += acc[_i][_j][_q];                \
            acc[_i][_j][_q] = 0.0f;                            \
        }                                                      \
    } while (0)

// ---------------- main kernel ----------------
__global__ __launch_bounds__(NTH, 1) void router_kernel(
    const float* __restrict__ x,
    const float* __restrict__ b,
    float* __restrict__ out)
{
    extern __shared__ __align__(16) char dsmem[];
    float* biasS = (float*)dsmem;                 // [64]
    const uint32_t F16B = smem_u32(dsmem + 1024); // 2 fp16 A slots
    const uint32_t BB   = F16B + 2 * A16_SLOT;    // 2 B slots
    float* Cs = (float*)(dsmem + 1024);           // epilogue in A16 slot 0

    const int tid = threadIdx.x;
    const int wid = tid >> 5;
    const int lid = tid & 31;
    const int block_m = blockIdx.x * BM;
    const bool consumer = (wid < 8);

    // consumer warp grid: 4 (M) x 2 (N), warp tile 32x32
    const int wm = (wid & 3) * 32;
    const int wn = ((wid >> 2) & 1) * 32;

    // ldsm lane addressing
    const uint32_t lrow = (lid & 7) + ((lid >> 3) & 1) * 8;
    const uint32_t swz  = (lrow & 7) << 4;
    const uint32_t colb = (lid >> 4) * 16;
    const uint32_t arow0 = (wm + lrow) * 128;
    const uint32_t arow1 = arow0 + 16 * 128;
    const uint32_t brow0 = (wn + lrow) * 128;
    const uint32_t brow1 = brow0 + 16 * 128;

    // producer mapping (ptid 0..255): one row half (32 k) each
    const int ptid = tid & 255;
    const int pr   = ptid >> 1;           // row 0..127
    const int pcb  = (ptid & 1) * 64;     // fp16 byte col base (32 k * 2B)
    const float* xsrc = x + (size_t)(block_m + pr) * HIDDEN + (ptid & 1) * 32;

    float acc[2][4][4], sum[2][4][4];
#pragma unroll
    for (int i = 0; i < 2; i++)
#pragma unroll
        for (int j = 0; j < 4; j++)
#pragma unroll
            for (int q = 0; q < 4; q++) { acc[i][j][q] = 0.0f; sum[i][j][q] = 0.0f; }

    float4 ax[8];

    // producer: convert 8 chunks from ax into fp16 slot
#define CONV_TILE(base)                                                        \
    do {                                                                       \
        _Pragma("unroll")                                                      \
        for (int _j = 0; _j < 8; _j++) {                                       \
            float f0[4], rr[4];                                                \
            splitf16(ax[_j].x * SCALE_IN, f0[0], rr[0]);                       \
            splitf16(ax[_j].y * SCALE_IN, f0[1], rr[1]);                       \
            splitf16(ax[_j].z * SCALE_IN, f0[2], rr[2]);                       \
            splitf16(ax[_j].w * SCALE_IN, f0[3], rr[3]);                       \
            uint32_t u0a, u0b, u1a, u1b;                                       \
            PACK_F16X2(u0a, f0[0], f0[1]); PACK_F16X2(u0b, f0[2], f0[3]);      \
            PACK_F16X2(u1a, rr[0], rr[1]); PACK_F16X2(u1b, rr[2], rr[3]);      \
            const uint32_t _so = sw128((uint32_t)(pr * 128 + pcb + _j * 8));   \
            sts64((base) + 0 * A_TERM + _so, u0a, u0b);                        \
            sts64((base) + 1 * A_TERM + _so, u1a, u1b);                        \
        }                                                                      \
    } while (0)

#define CP_B(base, tile)                                                       \
    do {                                                                       \
        const unsigned char* _ws = g_wb + (size_t)(tile) * B_SLOT;             \
        _Pragma("unroll")                                                      \
        for (int _j = 0; _j < 4; _j++) {                                       \
            const int _idx = ptid + _j * 256;                                  \
            cp_async16((base) + _idx * 16, _ws + (size_t)_idx * 16);           \
        }                                                                      \
        CP_COMMIT();                                                           \
    } while (0)

#define PREFETCH_AX(tile)                                                      \
    do {                                                                       \
        const float* _xs = xsrc + (size_t)(tile) * TK;                         \
        _Pragma("unroll")                                                      \
        for (int _j = 0; _j < 8; _j++) ax[_j] = *(const float4*)(_xs + _j * 4);\
    } while (0)

    // ---- prologue (producers build tile 0, prefetch tile 1)
    if (!consumer) {
        PREFETCH_AX(0);
        CONV_TILE(F16B);          // slot 0
        CP_B(BB, 0);              // B slot 0
        PREFETCH_AX(1);
        CP_WAIT0();
    }
    if (tid < NEXP) biasS[tid] = b[tid];
    __syncthreads();

    // ---- main loop: period p: consumers MMA tile p; producers build tile p+1
    for (int p = 0; p < NT; ++p) {
        if (consumer) {
            mma_stage(F16B + (p & 1) * A16_SLOT, BB + (p & 1) * B_SLOT,
                      acc, arow0, arow1, brow0, brow1, colb, swz);
            DRAIN();
        } else if (p + 1 < NT) {
            const int s = (p + 1) & 1;
            CONV_TILE(F16B + s * A16_SLOT);
            CP_B(BB + s * B_SLOT, p + 1);
            if (p + 2 < NT) PREFETCH_AX(p + 2);
            CP_WAIT0();
        }
        __syncthreads();
    }

    // ---- consumers dump C = sum into Cs (A16 slot 0; last MMA read slot 1)
    if (consumer) {
#pragma unroll
        for (int im = 0; im < 2; im++)
#pragma unroll
            for (int n8 = 0; n8 < 4; n8++) {
                const int r0 = wm + im * 16 + (lid >> 2);
                const int c0 = wn + n8 * 8 + (lid & 3) * 2;
                *(float2*)&Cs[r0 * CRS + c0] = make_float2(sum[im][n8][0], sum[im][n8][1]);
                *(float2*)&Cs[(r0 + 8) * CRS + c0] = make_float2(sum[im][n8][2], sum[im][n8][3]);
            }
    }
    __syncthreads();

    if (tid < BM) {
        const int m  = tid;
        const int gm = block_m + m;
        float v[NEXP];
#pragma unroll
        for (int e = 0; e < NEXP; e++)
            v[e] = Cs[m * CRS + e] * SCALE_OUT + biasS[e];

        float* outR    = out;
        float* outWt   = out + (size_t)N_TOKENS * NEXP;
        float* outIdx  = outWt + (size_t)N_TOKENS * TOPK;
        float* outMask = outIdx + (size_t)N_TOKENS * TOPK;

        float* dst = outR + (size_t)gm * NEXP;
#pragma unroll
        for (int e = 0; e < NEXP; e += 4)
            *(float4*)(dst + e) = make_float4(v[e], v[e + 1], v[e + 2], v[e + 3]);

        // top-8, strict > (first index on ties, matching jax top_k)
        unsigned long long used = 0ull;
        float vals[TOPK]; int idxs[TOPK];
#pragma unroll
        for (int k = 0; k < TOPK; k++) {
            float best = -INFINITY; int bi = 0;
#pragma unroll
            for (int e = 0; e < NEXP; e++) {
                const bool free_e = !((used >> e) & 1ull);
                if (free_e && v[e] > best) { best = v[e]; bi = e; }
            }
            used |= 1ull << bi;
            vals[k] = best; idxs[k] = bi;
        }
        const float mx = vals[0];
        float ex[TOPK], s = 0.0f;
#pragma unroll
        for (int k = 0; k < TOPK; k++) { ex[k] = expf(vals[k] - mx); s += ex[k]; }
        const float inv = 1.0f / s;

        *(float4*)(outWt + (size_t)gm * TOPK) =
            make_float4(ex[0] * inv, ex[1] * inv, ex[2] * inv, ex[3] * inv);
        *(float4*)(outWt + (size_t)gm * TOPK + 4) =
            make_float4(ex[4] * inv, ex[5] * inv, ex[6] * inv, ex[7] * inv);
        *(float4*)(outIdx + (size_t)gm * TOPK) =
            make_float4((float)idxs[0], (float)idxs[1], (float)idxs[2], (float)idxs[3]);
        *(float4*)(outIdx + (size_t)gm * TOPK + 4) =
            make_float4((float)idxs[4], (float)idxs[5], (float)idxs[6], (float)idxs[7]);
#pragma unroll
        for (int k = 0; k < TOPK; k++)
            outMask[(size_t)(idxs[k] * TOPK + k) * N_TOKENS + gm] = 1.0f;
    }
}

extern "C" void kernel_launch(void* const* d_in, const int* in_sizes, int n_in,
                              void* d_out, int out_size)
{
    const float* x = (const float*)d_in[0];
    const float* W = (const float*)d_in[1];
    const float* b = (const float*)d_in[2];
    float* out = (float*)d_out;

    // zero the expert_mask region (rest of out fully overwritten)
    float* mask = out + (size_t)N_TOKENS * NEXP + 2 * (size_t)N_TOKENS * TOPK;
    cudaMemsetAsync(mask, 0, (size_t)NEXP * TOPK * N_TOKENS * sizeof(float), 0);

    wsplit_kernel<<<NT, 256>>>(W);

    cudaFuncSetAttribute(router_kernel,
                         cudaFuncAttributeMaxDynamicSharedMemorySize, SMEM_BYTES);
    router_kernel<<<N_TOKENS / BM, NTH, SMEM_BYTES>>>(x, b, out);
}